// round 9
// baseline (speedup 1.0000x reference)
#include <cuda_runtime.h>
#include <cuda_bf16.h>
#include <cuda_fp16.h>
#include <cstdint>
#include <math.h>

#define BB 64
#define CC 2048
#define CI 1024
#define NSP 512   // H*W

typedef unsigned short u16;
typedef uint32_t u32;

// ---------------- scratch (static device globals) -----------------------------
__device__ u16 g_xTh[(size_t)BB * NSP * CC];
__device__ u16 g_xTl[(size_t)BB * NSP * CC];
__device__ u16 g_Wth[(size_t)CI * CC], g_Wtl[(size_t)CI * CC];
__device__ u16 g_Wph[(size_t)CI * CC], g_Wpl[(size_t)CI * CC];
__device__ u16 g_Wgf[(size_t)CI * CC];
__device__ u16 g_Wof[(size_t)CC * CI];
__device__ u16 g_thh[(size_t)BB * NSP * CI], g_thl[(size_t)BB * NSP * CI];
__device__ u16 g_phh[(size_t)BB * NSP * CI], g_phl[(size_t)BB * NSP * CI];
__device__ u16 g_gf [(size_t)BB * CI * NSP];
__device__ float g_f [(size_t)BB * NSP * NSP];
__device__ u16 g_ath[(size_t)BB * NSP * NSP];
__device__ u16 g_yT [(size_t)BB * NSP * CI];
__device__ float g_pS[(size_t)128 * CC];   // per-(slot,channel) partial sums
__device__ float g_pQ[(size_t)128 * CC];   // per-(slot,channel) partial sumsq
__device__ float g_mean[CC];
__device__ float g_rstd[CC];

// ---------------- helpers ------------------------------------------------------
__device__ __forceinline__ u32 smem_u32(const void* p) {
    u32 a;
    asm("{ .reg .u64 t; cvta.to.shared.u64 t, %1; cvt.u32.u64 %0, t; }" : "=r"(a) : "l"(p));
    return a;
}
__device__ __forceinline__ void split_fp(float v, u16& h, u16& l) {
    __half hh = __float2half_rn(v);
    h = __half_as_ushort(hh);
    l = __half_as_ushort(__float2half_rn(v - __half2float(hh)));
}
__device__ __forceinline__ void ldsm_x4(u32* r, u32 addr) {
    asm volatile("ldmatrix.sync.aligned.m8n8.x4.shared.b16 {%0,%1,%2,%3}, [%4];"
                 : "=r"(r[0]), "=r"(r[1]), "=r"(r[2]), "=r"(r[3]) : "r"(addr));
}
__device__ __forceinline__ void mma16816(float* c, const u32* a, u32 b0, u32 b1) {
    asm volatile("mma.sync.aligned.m16n8k16.row.col.f32.f16.f16.f32 "
                 "{%0,%1,%2,%3}, {%4,%5,%6,%7}, {%8,%9}, {%0,%1,%2,%3};"
                 : "+f"(c[0]), "+f"(c[1]), "+f"(c[2]), "+f"(c[3])
                 : "r"(a[0]), "r"(a[1]), "r"(a[2]), "r"(a[3]), "r"(b0), "r"(b1));
}

// copy ROWSx32 u16 chunk (row stride K) into blocked smem layout
template<int ROWS>
__device__ __forceinline__ void cpa(u32 dst, const u16* __restrict__ src,
                                    int K, int k0, int tid) {
    constexpr int RT  = ROWS / 8;
    constexpr int PER = (ROWS * 4) / 256;
#pragma unroll
    for (int i = 0; i < PER; ++i) {
        int u  = tid + i * 256;
        int r  = u >> 2;
        int kb = u & 3;
        const void* gp = src + (size_t)r * K + k0 + kb * 8;
        u32 dp = dst + (u32)(((kb * RT + (r >> 3)) << 7) + ((r & 7) << 4));
        asm volatile("cp.async.cg.shared.global [%0], [%1], 16;" :: "r"(dp), "l"(gp));
    }
}

// ---------------- HMMA GEMM (all fp16) ------------------------------------------
// D[m][n] = sum_k A[m][k]*B[n][k].
// MT: CTA M-tile (128 or 64). N-tile fixed 256. 8 warps: MT=128 -> 2x4 (warp 64x64);
// MT=64 -> 1x8 (warp 64x32). k-chunk 32, 4 stages, 1 CTA/SM.
// NMMA=3: A h/l, B h/l (AhBh+AlBh+AhBl).  NMMA=1: single*single.
// OUT: 0 fp32, 1 fp16 hi/lo pair, 2 fp16 single.  BIAS: 0 none, 1 row(M), 2 col(N).
// STATS=1 (with OUT==0): emit deterministic per-(slot,channel) partial sum/sumsq.
template<int MT, int NMMA, int OUT, int BIAS, int STATS>
__global__ void __launch_bounds__(256, 1)
hgemm(const u16* __restrict__ Ah, const u16* __restrict__ Al,
      const u16* __restrict__ Bh, const u16* __restrict__ Bl,
      void* __restrict__ Co, u16* __restrict__ Colo,
      const float* __restrict__ bias,
      float* __restrict__ gS, float* __restrict__ gQ,
      int K, int ldo, long bsA, long bsB, long bsC)
{
    extern __shared__ char smem[];
    const u32 sm0 = smem_u32(smem);
    constexpr int WN  = (MT == 128) ? 4 : 8;     // warps along N
    constexpr int NF  = 32 / WN;                 // 8x8 n-frags per warp
    constexpr int NP  = NF / 2;
    constexpr int ART = MT / 8;
    constexpr u32 ABY = (u32)MT * 64;            // bytes per A operand chunk
    constexpr u32 BOFF  = ABY * ((NMMA == 3) ? 2u : 1u);
    constexpr u32 STAGE = BOFF + 16384u * ((NMMA == 3) ? 2u : 1u);

    const int tid = threadIdx.x, lane = tid & 31, wid = tid >> 5;
    const int wm = wid / WN, wn = wid % WN;
    const int m0 = blockIdx.y * MT, n0 = blockIdx.x * 256, b = blockIdx.z;

    const u16* pAh = Ah + (size_t)b * bsA + (size_t)m0 * K;
    const u16* pAl = (NMMA == 3) ? (Al + (size_t)b * bsA + (size_t)m0 * K) : nullptr;
    const u16* pBh = Bh + (size_t)b * bsB + (size_t)n0 * K;
    const u16* pBl = (NMMA == 3) ? (Bl + (size_t)b * bsB + (size_t)n0 * K) : nullptr;

    const int nch = K >> 5;

    float acc[4][NF][4];
#pragma unroll
    for (int i = 0; i < 4; ++i)
#pragma unroll
        for (int j = 0; j < NF; ++j)
#pragma unroll
            for (int q = 0; q < 4; ++q) acc[i][j][q] = 0.f;

    // prologue: prefetch chunks 0..2
#pragma unroll
    for (int p = 0; p < 3; ++p) {
        u32 sb = sm0 + (u32)(p & 3) * STAGE;
        cpa<MT>(sb, pAh, K, p * 32, tid);
        if (NMMA == 3) cpa<MT>(sb + ABY, pAl, K, p * 32, tid);
        cpa<256>(sb + BOFF, pBh, K, p * 32, tid);
        if (NMMA == 3) cpa<256>(sb + BOFF + 16384u, pBl, K, p * 32, tid);
        asm volatile("cp.async.commit_group;");
    }

    const int ga = lane >> 3;
    const int lrow = lane & 7;

    for (int ks = 0; ks < nch; ++ks) {
        asm volatile("cp.async.wait_group 2;" ::: "memory");
        __syncthreads();
        {
            const int pf = ks + 3;
            if (pf < nch) {
                u32 sb = sm0 + (u32)(pf & 3) * STAGE;
                cpa<MT>(sb, pAh, K, pf * 32, tid);
                if (NMMA == 3) cpa<MT>(sb + ABY, pAl, K, pf * 32, tid);
                cpa<256>(sb + BOFF, pBh, K, pf * 32, tid);
                if (NMMA == 3) cpa<256>(sb + BOFF + 16384u, pBl, K, pf * 32, tid);
            }
            asm volatile("cp.async.commit_group;");
        }

        const u32 sb = sm0 + (u32)(ks & 3) * STAGE;
#pragma unroll
        for (int kk = 0; kk < 2; ++kk) {
            const int k8 = 2 * kk + (ga >> 1);
            // ---- A fragments ----
            u32 ah[4][4], al[4][4];
#pragma unroll
            for (int mf = 0; mf < 4; ++mf) {
                const int m8 = wm * 8 + mf * 2 + (ga & 1);
                u32 ad = sb + (u32)(((k8 * ART + m8) << 7) + (lrow << 4));
                ldsm_x4(ah[mf], ad);
                if (NMMA == 3) ldsm_x4(al[mf], ad + ABY);
            }
            // ---- B fragments: double-buffered ----
            u32 bt[2][4], bs[2][4];
            {
                const int n8 = wn * NF + (ga & 1);
                u32 bd = sb + BOFF + (u32)(((k8 * 32 + n8) << 7) + (lrow << 4));
                ldsm_x4(bt[0], bd);
                if (NMMA == 3) ldsm_x4(bs[0], bd + 16384u);
            }
#pragma unroll
            for (int np = 0; np < NP; ++np) {
                const int cur = np & 1;
                if (np < NP - 1) {
                    const int n8 = wn * NF + (np + 1) * 2 + (ga & 1);
                    u32 bd = sb + BOFF + (u32)(((k8 * 32 + n8) << 7) + (lrow << 4));
                    ldsm_x4(bt[cur ^ 1], bd);
                    if (NMMA == 3) ldsm_x4(bs[cur ^ 1], bd + 16384u);
                }
                // pass 1: ah * bt
#pragma unroll
                for (int mf = 0; mf < 4; ++mf) {
                    mma16816(acc[mf][2*np],   ah[mf], bt[cur][0], bt[cur][2]);
                    mma16816(acc[mf][2*np+1], ah[mf], bt[cur][1], bt[cur][3]);
                }
                if (NMMA == 3) {
                    // pass 2: al * bt
#pragma unroll
                    for (int mf = 0; mf < 4; ++mf) {
                        mma16816(acc[mf][2*np],   al[mf], bt[cur][0], bt[cur][2]);
                        mma16816(acc[mf][2*np+1], al[mf], bt[cur][1], bt[cur][3]);
                    }
                    // pass 3: ah * bs
#pragma unroll
                    for (int mf = 0; mf < 4; ++mf) {
                        mma16816(acc[mf][2*np],   ah[mf], bs[cur][0], bs[cur][2]);
                        mma16816(acc[mf][2*np+1], ah[mf], bs[cur][1], bs[cur][3]);
                    }
                }
            }
        }
    }

    // ---- epilogue ----
    const int erow = lane >> 2;
    const int ecol = (lane & 3) * 2;
    float* spart = reinterpret_cast<float*>(smem);   // [WN][MT][2] (STATS only)

#pragma unroll
    for (int mf = 0; mf < 4; ++mf) {
        const int gm = m0 + wm * 64 + mf * 16 + erow;
        float rb0 = 0.f, rb1 = 0.f;
        if (BIAS == 1) { rb0 = bias[gm]; rb1 = bias[gm + 8]; }
        float s0 = 0.f, q0 = 0.f, s1 = 0.f, q1 = 0.f;
#pragma unroll
        for (int nf = 0; nf < NF; ++nf) {
            const int gn = n0 + wn * (256 / WN) + nf * 8 + ecol;
            float cb0 = 0.f, cb1 = 0.f;
            if (BIAS == 2) { cb0 = bias[gn]; cb1 = bias[gn + 1]; }
            float v00 = acc[mf][nf][0] + rb0 + cb0;
            float v01 = acc[mf][nf][1] + rb0 + cb1;
            float v10 = acc[mf][nf][2] + rb1 + cb0;
            float v11 = acc[mf][nf][3] + rb1 + cb1;
            if (STATS) {
                s0 += v00 + v01;  q0 += v00 * v00 + v01 * v01;
                s1 += v10 + v11;  q1 += v10 * v10 + v11 * v11;
            }
            if (OUT == 0) {
                float* C = (float*)Co + (size_t)b * bsC + (size_t)gm * ldo + gn;
                *reinterpret_cast<float2*>(C) = make_float2(v00, v01);
                *reinterpret_cast<float2*>(C + 8 * (size_t)ldo) = make_float2(v10, v11);
            } else if (OUT == 1) {
                u16* Ch = (u16*)Co + (size_t)b * bsC + (size_t)gm * ldo + gn;
                u16* Cl = Colo     + (size_t)b * bsC + (size_t)gm * ldo + gn;
                u16 h0, l0, h1, l1;
                split_fp(v00, h0, l0); split_fp(v01, h1, l1);
                *reinterpret_cast<u32*>(Ch) = (u32)h0 | ((u32)h1 << 16);
                *reinterpret_cast<u32*>(Cl) = (u32)l0 | ((u32)l1 << 16);
                split_fp(v10, h0, l0); split_fp(v11, h1, l1);
                *reinterpret_cast<u32*>(Ch + 8 * (size_t)ldo) = (u32)h0 | ((u32)h1 << 16);
                *reinterpret_cast<u32*>(Cl + 8 * (size_t)ldo) = (u32)l0 | ((u32)l1 << 16);
            } else {
                u16* C = (u16*)Co + (size_t)b * bsC + (size_t)gm * ldo + gn;
                u16 h0 = __half_as_ushort(__float2half_rn(v00));
                u16 h1 = __half_as_ushort(__float2half_rn(v01));
                *reinterpret_cast<u32*>(C) = (u32)h0 | ((u32)h1 << 16);
                h0 = __half_as_ushort(__float2half_rn(v10));
                h1 = __half_as_ushort(__float2half_rn(v11));
                *reinterpret_cast<u32*>(C + 8 * (size_t)ldo) = (u32)h0 | ((u32)h1 << 16);
            }
        }
        if (STATS) {
            // reduce over the 4 lanes sharing erow (lane^1, lane^2 stay in group)
#pragma unroll
            for (int o = 1; o < 4; o <<= 1) {
                s0 += __shfl_xor_sync(0xffffffffu, s0, o);
                q0 += __shfl_xor_sync(0xffffffffu, q0, o);
                s1 += __shfl_xor_sync(0xffffffffu, s1, o);
                q1 += __shfl_xor_sync(0xffffffffu, q1, o);
            }
            if ((lane & 3) == 0) {
                const int r = wm * 64 + mf * 16 + erow;     // local row in [0,MT)
                spart[((size_t)wn * MT + r) * 2 + 0] = s0;
                spart[((size_t)wn * MT + r) * 2 + 1] = q0;
                spart[((size_t)wn * MT + r + 8) * 2 + 0] = s1;
                spart[((size_t)wn * MT + r + 8) * 2 + 1] = q1;
            }
        }
    }
    if (STATS) {
        __syncthreads();
        if (tid < MT) {
            float s = 0.f, q = 0.f;
#pragma unroll
            for (int w = 0; w < WN; ++w) {
                s += spart[((size_t)w * MT + tid) * 2 + 0];
                q += spart[((size_t)w * MT + tid) * 2 + 1];
            }
            const int slot = blockIdx.x * BB + b;          // 0..127
            gS[(size_t)slot * CC + m0 + tid] = s;
            gQ[(size_t)slot * CC + m0 + tid] = q;
        }
    }
}

// ---------------- prepass: convert all 4 weights in ONE launch ------------------
__global__ void __launch_bounds__(256)
wsplit_kernel(const float* __restrict__ Wt, const float* __restrict__ Wp,
              const float* __restrict__ Wg, const float* __restrict__ Wo,
              u16* wth, u16* wtl, u16* wph, u16* wpl,
              u16* wgf, u16* wof)
{
    int i = blockIdx.x * 256 + threadIdx.x;
    u16 h, l;
    switch (blockIdx.y) {
        case 0: split_fp(Wt[i], h, l); wth[i] = h; wtl[i] = l; break;
        case 1: split_fp(Wp[i], h, l); wph[i] = h; wpl[i] = l; break;
        case 2: wgf[i] = __half_as_ushort(__float2half_rn(Wg[i])); break;
        default: wof[i] = __half_as_ushort(__float2half_rn(Wo[i])); break;
    }
}

// x [b][c][n] -> xT fp16 h/l [b][n][c], 64c x 32n tiles, uint4 stores
__global__ void __launch_bounds__(256)
xpose_split_kernel(const float* __restrict__ x, u16* __restrict__ xh,
                   u16* __restrict__ xl) {
    __shared__ float t[32][65];   // [n][c]
    const int b = blockIdx.z;
    const int n0 = blockIdx.x * 32, c0 = blockIdx.y * 64;
    const int tid = threadIdx.x;
    // load 64 c-rows x 32 n-cols
    {
        const int col = tid & 31;
        const float* xp = x + ((size_t)b * CC + c0) * NSP + n0 + col;
#pragma unroll
        for (int i = 0; i < 8; ++i) {
            int r = (tid >> 5) + i * 8;   // 0..63
            t[col][r] = xp[(size_t)r * NSP];
        }
    }
    __syncthreads();
    // store: thread -> n = tid>>3, c-group = (tid&7)*8 (8 consecutive c)
    {
        const int n  = tid >> 3;
        const int cg = (tid & 7) * 8;
        u32 vh[4], vl[4];
#pragma unroll
        for (int j = 0; j < 4; ++j) {
            u16 h0, l0, h1, l1;
            split_fp(t[n][cg + 2 * j],     h0, l0);
            split_fp(t[n][cg + 2 * j + 1], h1, l1);
            vh[j] = (u32)h0 | ((u32)h1 << 16);
            vl[j] = (u32)l0 | ((u32)l1 << 16);
        }
        const size_t idx = ((size_t)b * NSP + n0 + n) * CC + c0 + cg;
        *reinterpret_cast<uint4*>(xh + idx) = make_uint4(vh[0], vh[1], vh[2], vh[3]);
        *reinterpret_cast<uint4*>(xl + idx) = make_uint4(vl[0], vl[1], vl[2], vl[3]);
    }
}

// ---------------- softmax over rows of 512 -> fp16 single -----------------------
__global__ void __launch_bounds__(256)
softmax_kernel(const float* __restrict__ f, u16* __restrict__ ah) {
    const size_t off = (size_t)blockIdx.x * NSP;
    const float* p = f + off;
    const int t = threadIdx.x;
    float v0 = p[t];
    float v1 = p[t + 256];

    __shared__ float red[8];
    float m = fmaxf(v0, v1);
#pragma unroll
    for (int o = 16; o; o >>= 1) m = fmaxf(m, __shfl_xor_sync(0xffffffffu, m, o));
    if ((t & 31) == 0) red[t >> 5] = m;
    __syncthreads();
    float M = red[0];
#pragma unroll
    for (int i = 1; i < 8; ++i) M = fmaxf(M, red[i]);
    __syncthreads();

    float e0 = expf(v0 - M);
    float e1 = expf(v1 - M);
    float s = e0 + e1;
#pragma unroll
    for (int o = 16; o; o >>= 1) s += __shfl_xor_sync(0xffffffffu, s, o);
    if ((t & 31) == 0) red[t >> 5] = s;
    __syncthreads();
    float S = 0.f;
#pragma unroll
    for (int i = 0; i < 8; ++i) S += red[i];

    const float inv = 1.f / S;
    ah[off + t]       = __half_as_ushort(__float2half_rn(e0 * inv));
    ah[off + t + 256] = __half_as_ushort(__float2half_rn(e1 * inv));
}

// ---------------- BN finalize (from per-slot partials) & apply ------------------
__global__ void __launch_bounds__(256)
bn_finalize_kernel(const float* __restrict__ gS, const float* __restrict__ gQ,
                   float* __restrict__ mean, float* __restrict__ rstd) {
    const int o = blockIdx.x * 256 + threadIdx.x;   // < 2048
    float s = 0.f, q = 0.f;
    for (int sl = 0; sl < 128; ++sl) {
        s += gS[(size_t)sl * CC + o];
        q += gQ[(size_t)sl * CC + o];
    }
    const double cnt = (double)(BB * NSP);
    const double mu  = (double)s / cnt;
    const double var = (double)q / cnt - mu * mu;
    mean[o] = (float)mu;
    rstd[o] = (float)rsqrt(var + 1e-5);
}

__global__ void __launch_bounds__(256)
bn_apply_kernel(float* __restrict__ out, const float* __restrict__ x,
                const float* __restrict__ mean, const float* __restrict__ rstd,
                const float* __restrict__ gamma, const float* __restrict__ beta) {
    const long i4 = (long)blockIdx.x * blockDim.x + threadIdx.x;
    const long e = i4 * 4;
    const int c = (int)((e >> 9) & (CC - 1));
    const float mu = mean[c];
    const float rs = rstd[c];
    const float ga = gamma[c];
    const float be = beta[c];
    float4 w  = *reinterpret_cast<const float4*>(&out[e]);
    float4 xv = *reinterpret_cast<const float4*>(&x[e]);
    w.x = (w.x - mu) * rs * ga + be + xv.x;
    w.y = (w.y - mu) * rs * ga + be + xv.y;
    w.z = (w.z - mu) * rs * ga + be + xv.z;
    w.w = (w.w - mu) * rs * ga + be + xv.w;
    *reinterpret_cast<float4*>(&out[e]) = w;
}

// -------------------------------------------------------------------------------
extern "C" void kernel_launch(void* const* d_in, const int* in_sizes, int n_in,
                              void* d_out, int out_size)
{
    const float* x     = (const float*)d_in[0];
    const float* Wg    = (const float*)d_in[1];
    const float* bg    = (const float*)d_in[2];
    const float* Wt    = (const float*)d_in[3];
    const float* bt    = (const float*)d_in[4];
    const float* Wp    = (const float*)d_in[5];
    const float* bp    = (const float*)d_in[6];
    const float* Wo    = (const float*)d_in[7];
    const float* bo    = (const float*)d_in[8];
    const float* gamma = (const float*)d_in[9];
    const float* beta  = (const float*)d_in[10];
    float* out = (float*)d_out;

    u16 *xTh, *xTl, *Wth, *Wtl, *Wph, *Wpl, *Wgf, *Wof;
    u16 *thh, *thl, *phh, *phl, *gf, *ath, *yT;
    float *f, *pS, *pQ, *mean, *rstd;
    cudaGetSymbolAddress((void**)&xTh, g_xTh); cudaGetSymbolAddress((void**)&xTl, g_xTl);
    cudaGetSymbolAddress((void**)&Wth, g_Wth); cudaGetSymbolAddress((void**)&Wtl, g_Wtl);
    cudaGetSymbolAddress((void**)&Wph, g_Wph); cudaGetSymbolAddress((void**)&Wpl, g_Wpl);
    cudaGetSymbolAddress((void**)&Wgf, g_Wgf); cudaGetSymbolAddress((void**)&Wof, g_Wof);
    cudaGetSymbolAddress((void**)&thh, g_thh); cudaGetSymbolAddress((void**)&thl, g_thl);
    cudaGetSymbolAddress((void**)&phh, g_phh); cudaGetSymbolAddress((void**)&phl, g_phl);
    cudaGetSymbolAddress((void**)&gf,  g_gf);
    cudaGetSymbolAddress((void**)&ath, g_ath);
    cudaGetSymbolAddress((void**)&yT,  g_yT);
    cudaGetSymbolAddress((void**)&f,   g_f);
    cudaGetSymbolAddress((void**)&pS,  g_pS);  cudaGetSymbolAddress((void**)&pQ, g_pQ);
    cudaGetSymbolAddress((void**)&mean, g_mean); cudaGetSymbolAddress((void**)&rstd, g_rstd);

    const int SM3_128 = 4 * 49152;  // MT128, NMMA3
    const int SM3_64  = 4 * 40960;  // MT64,  NMMA3
    const int SM1_128 = 4 * 24576;  // MT128, NMMA1
    cudaFuncSetAttribute((const void*)hgemm<128,3,1,2,0>, cudaFuncAttributeMaxDynamicSharedMemorySize, SM3_128);
    cudaFuncSetAttribute((const void*)hgemm<64,3,0,0,0>,  cudaFuncAttributeMaxDynamicSharedMemorySize, SM3_64);
    cudaFuncSetAttribute((const void*)hgemm<128,1,2,1,0>, cudaFuncAttributeMaxDynamicSharedMemorySize, SM1_128);
    cudaFuncSetAttribute((const void*)hgemm<128,1,2,0,0>, cudaFuncAttributeMaxDynamicSharedMemorySize, SM1_128);
    cudaFuncSetAttribute((const void*)hgemm<128,1,0,1,1>, cudaFuncAttributeMaxDynamicSharedMemorySize, SM1_128);

    const long bs_xT = (long)NSP * CC;
    const long bs_pT = (long)NSP * CI;
    const long bs_g  = (long)CI * NSP;
    const long bs_f  = (long)NSP * NSP;
    const long bs_o  = (long)CC * NSP;

    // 0) weights convert (one launch)
    wsplit_kernel<<<dim3((CI * CC) / 256, 4), 256>>>(
        Wt, Wp, Wg, Wo, Wth, Wtl, Wph, Wpl, Wgf, Wof);
    // 1) x -> xT fp16 h/l
    xpose_split_kernel<<<dim3(NSP / 32, CC / 64, BB), 256>>>(x, xTh, xTl);

    // 2) g[ci][m] = Wg . xT + bg   (1-MMA fp16, row bias, fp16 out)
    hgemm<128,1,2,1,0><<<dim3(NSP/256, CI/128, BB), 256, SM1_128>>>(
        Wgf, nullptr, xTh, nullptr, gf, nullptr, bg, nullptr, nullptr,
        CC, NSP, 0L, bs_xT, bs_g);
    // 3) thT[n][ci] = xT . Wt + bt  (3-MMA fp16, col bias, fp16 h/l out)
    hgemm<128,3,1,2,0><<<dim3(CI/256, NSP/128, BB), 256, SM3_128>>>(
        xTh, xTl, Wth, Wtl, thh, thl, bt, nullptr, nullptr,
        CC, CI, bs_xT, 0L, bs_pT);
    // 4) phT
    hgemm<128,3,1,2,0><<<dim3(CI/256, NSP/128, BB), 256, SM3_128>>>(
        xTh, xTl, Wph, Wpl, phh, phl, bp, nullptr, nullptr,
        CC, CI, bs_xT, 0L, bs_pT);
    // 5) f[n][m] = thT . phT        (3-MMA fp16, MT=64 for full waves, fp32 out)
    hgemm<64,3,0,0,0><<<dim3(NSP/256, NSP/64, BB), 256, SM3_64>>>(
        thh, thl, phh, phl, f, nullptr, nullptr, nullptr, nullptr,
        CI, NSP, bs_pT, bs_pT, bs_f);
    // 6) softmax -> attn fp16 single
    softmax_kernel<<<BB * NSP, 256>>>(f, ath);
    // 7) yT[n][ci] = attn . g       (1-MMA fp16, fp16 out)
    hgemm<128,1,2,0,0><<<dim3(CI/256, NSP/128, BB), 256, SM1_128>>>(
        ath, nullptr, gf, nullptr, yT, nullptr, nullptr, nullptr, nullptr,
        NSP, CI, bs_f, bs_g, bs_pT);
    // 8) out[o][n] = Wo . yT + bo   (1-MMA fp16, fp32 -> d_out, + BN partials)
    hgemm<128,1,0,1,1><<<dim3(NSP/256, CC/128, BB), 256, SM1_128>>>(
        Wof, nullptr, yT, nullptr, out, nullptr, bo, pS, pQ,
        CI, NSP, 0L, bs_pT, bs_o);

    // 9) BN finalize + apply + residual
    bn_finalize_kernel<<<CC / 256, 256>>>(pS, pQ, mean, rstd);
    {
        const long total4 = (long)BB * CC * NSP / 4;
        bn_apply_kernel<<<(unsigned)(total4 / 256), 256>>>(out, x, mean, rstd, gamma, beta);
    }
}